// round 9
// baseline (speedup 1.0000x reference)
#include <cuda_runtime.h>

// ---------------- problem constants (hardcoded from reference) -------------
#define CBSZ  4
#define CQLEN 1024
#define CKLEN 2048
#define CNH   16
#define CDH   64
#define CDM   1024
#define CMEM  1024   // MEM_LEN = KLEN - QLEN

// ---------------- scratch (device globals; no allocations allowed) ---------
__device__ float g_q [CBSZ * CQLEN * CDM];            // 16 MB  q[b,i,h*64+d]
__device__ float g_kv[(long)CBSZ * CKLEN * 2 * CDM];  // 64 MB  kv[b,j, (k|v)]
__device__ float g_rk[CKLEN * CDM];                   //  8 MB  rk[m,h*64+d]
__device__ float g_av[CBSZ * CQLEN * CDM];            // 16 MB  attn_vec

// ======================= SGEMM: C = A @ B (row-major) ======================
// 128x128 block tile, BK=16, 256 threads, 8x8 per thread.
// All dims used here are multiples of 128 / 16 -> no bounds checks.
__global__ __launch_bounds__(256, 2)
void sgemm128(const float* __restrict__ A, const float* __restrict__ B,
              float* __restrict__ C, int N, int K, long sA, long sC) {
    __shared__ float As[16][128];
    __shared__ float Bs[16][132];

    const float* Ab = A + (long)blockIdx.z * sA;
    float*       Cb = C + (long)blockIdx.z * sC;
    const int m0 = blockIdx.y * 128;
    const int n0 = blockIdx.x * 128;
    const int tid = threadIdx.x;
    const int tr = tid >> 4;      // 0..15
    const int tc = tid & 15;      // 0..15

    float acc[8][8];
#pragma unroll
    for (int u = 0; u < 8; ++u)
#pragma unroll
        for (int w = 0; w < 8; ++w) acc[u][w] = 0.f;

    for (int k0 = 0; k0 < K; k0 += 16) {
        // A tile: 128 rows x 16 cols, stored transposed As[k][m]
#pragma unroll
        for (int it = 0; it < 2; ++it) {
            int idx = it * 256 + tid;          // float4 index, 512 total
            int r  = idx >> 2;                 // 0..127
            int c4 = (idx & 3) << 2;           // 0,4,8,12
            float4 v = *(const float4*)&Ab[(long)(m0 + r) * K + k0 + c4];
            As[c4 + 0][r] = v.x; As[c4 + 1][r] = v.y;
            As[c4 + 2][r] = v.z; As[c4 + 3][r] = v.w;
        }
        // B tile: 16 rows x 128 cols
#pragma unroll
        for (int it = 0; it < 2; ++it) {
            int idx = it * 256 + tid;
            int r  = idx >> 5;                 // 0..15
            int c4 = (idx & 31) << 2;          // 0..124
            *(float4*)&Bs[r][c4] = *(const float4*)&B[(long)(k0 + r) * N + n0 + c4];
        }
        __syncthreads();
#pragma unroll
        for (int kk = 0; kk < 16; ++kk) {
            float a[8], bb[8];
            *(float4*)&a[0]  = *(const float4*)&As[kk][tr * 8];
            *(float4*)&a[4]  = *(const float4*)&As[kk][tr * 8 + 4];
            *(float4*)&bb[0] = *(const float4*)&Bs[kk][tc * 8];
            *(float4*)&bb[4] = *(const float4*)&Bs[kk][tc * 8 + 4];
#pragma unroll
            for (int u = 0; u < 8; ++u)
#pragma unroll
                for (int w = 0; w < 8; ++w)
                    acc[u][w] = fmaf(a[u], bb[w], acc[u][w]);
        }
        __syncthreads();
    }
#pragma unroll
    for (int u = 0; u < 8; ++u) {
        long row = m0 + tr * 8 + u;
        float4 o0 = make_float4(acc[u][0], acc[u][1], acc[u][2], acc[u][3]);
        float4 o1 = make_float4(acc[u][4], acc[u][5], acc[u][6], acc[u][7]);
        *(float4*)&Cb[row * N + n0 + tc * 8]     = o0;
        *(float4*)&Cb[row * N + n0 + tc * 8 + 4] = o1;
    }
}

// =================== Fused rel-attention (flash-style) =====================
// score[i,j] = ( q_i·k_j + q_i·rk_m + rwb·k_j + rrb·rk_m ) * 1/8,
//   m = j - i + 1023, valid iff j <= i + 1024 (== rel-shift in-range region).
// Block: one (b, h, 64-query i-tile). j-tiles of 64. rk band of 128 rows.
// Thread map: ty=tid/16 tx=tid%16; thread covers rows {ty+16u}, cols {tx+16a}.
// -> rk band row index = (tx - ty + 15) + 16*(a-u+3), steps by 1 across tx
//    (bank-friendly with stride-65 SMEM rows).
__global__ __launch_bounds__(256, 2)
void attn_kernel(const float* __restrict__ rwbias, const float* __restrict__ rrbias) {
    extern __shared__ float smf[];
    float* sq  = smf;               // 64 x 65
    float* sk  = sq  + 64 * 65;     // 64 x 65
    float* sp  = sk  + 64 * 65;     // 64 x 65 (probabilities)
    float* srk = sp  + 64 * 65;     // 128 x 65 (rk band)
    float* sv  = srk + 128 * 65;    // 64 x 68 (16B-aligned rows for float4)
    float* ck  = sv  + 64 * 68;     // 64   rwb·k_j
    float* crk = ck  + 64;          // 128  rrb·rk_m
    float* rwb = crk + 128;         // 64
    float* rrb = rwb + 64;          // 64

    const int it0 = blockIdx.x;     // i-tile (0..15)
    const int h   = blockIdx.y;
    const int b   = blockIdx.z;
    const int i0  = it0 * 64;
    const int tid = threadIdx.x;
    const int ty  = tid >> 4;       // 0..15
    const int tx  = tid & 15;       // 0..15

    if (tid < 64)        rwb[tid]      = rwbias[h * 64 + tid];
    else if (tid < 128)  rrb[tid - 64] = rrbias[h * 64 + (tid - 64)];

    // q tile (raw q; biases folded via ck/crk scalars)
#pragma unroll
    for (int e = 0; e < 16; ++e) {
        int idx = e * 256 + tid;
        int rr = idx >> 6, d = idx & 63;
        sq[rr * 65 + d] = g_q[(long)(b * CQLEN + i0 + rr) * CDM + h * CDH + d];
    }
    __syncthreads();

    float o[4][4];
    float mrun[4], lrun[4];
#pragma unroll
    for (int u = 0; u < 4; ++u) {
        mrun[u] = -1e30f; lrun[u] = 0.f;
#pragma unroll
        for (int w = 0; w < 4; ++w) o[u][w] = 0.f;
    }

    const int rb  = tx - ty + 15;        // band base row (0..30)
    const int njt = it0 + 17;            // last tile with any valid j

    for (int jt = 0; jt < njt; ++jt) {
        const int j0 = jt * 64;
        const int m0 = j0 - i0 + 960;    // band start (>= 0 always)

        // load k, v tiles
#pragma unroll
        for (int e = 0; e < 16; ++e) {
            int idx = e * 256 + tid;
            int rr = idx >> 6, d = idx & 63;
            long base = (long)(b * CKLEN + j0 + rr) * (2 * CDM) + h * CDH + d;
            sk[rr * 65 + d] = g_kv[base];
            sv[rr * 68 + d] = g_kv[base + CDM];
        }
        // load rk band (128 rows; clamp — overflow rows only feed masked entries)
#pragma unroll
        for (int e = 0; e < 32; ++e) {
            int idx = e * 256 + tid;
            int rr = idx >> 6, d = idx & 63;
            int m = m0 + rr; if (m > CKLEN - 1) m = CKLEN - 1;
            srk[rr * 65 + d] = g_rk[(long)m * CDM + h * CDH + d];
        }
        __syncthreads();

        // per-column bias scalars
        if (tid < 64) {
            float s = 0.f;
            for (int d = 0; d < 64; ++d) s = fmaf(rwb[d], sk[tid * 65 + d], s);
            ck[tid] = s;
        } else if (tid < 192) {
            int t = tid - 64;
            float s = 0.f;
            for (int d = 0; d < 64; ++d) s = fmaf(rrb[d], srk[t * 65 + d], s);
            crk[t] = s;
        }
        __syncthreads();

        // scores: two length-64 dots per (i,j)
        float s1[4][4], s2[4][4];
#pragma unroll
        for (int u = 0; u < 4; ++u)
#pragma unroll
            for (int a = 0; a < 4; ++a) { s1[u][a] = 0.f; s2[u][a] = 0.f; }

#pragma unroll 4
        for (int d = 0; d < 64; ++d) {
            float qv[4], kvv[4], rv[7];
#pragma unroll
            for (int u = 0; u < 4; ++u) qv[u]  = sq[(ty + 16 * u) * 65 + d];
#pragma unroll
            for (int a = 0; a < 4; ++a) kvv[a] = sk[(tx + 16 * a) * 65 + d];
#pragma unroll
            for (int t = 0; t < 7; ++t) rv[t]  = srk[(rb + 16 * t) * 65 + d];
#pragma unroll
            for (int u = 0; u < 4; ++u)
#pragma unroll
                for (int a = 0; a < 4; ++a) {
                    s1[u][a] = fmaf(qv[u], kvv[a],        s1[u][a]);
                    s2[u][a] = fmaf(qv[u], rv[a - u + 3], s2[u][a]);
                }
        }

        // online softmax (row reduce across the 16 tx lanes of each half-warp)
        const float scl = 0.125f;
#pragma unroll
        for (int u = 0; u < 4; ++u) {
            const int ig = i0 + ty + 16 * u;
            float sr[4], tmax = -1e30f;
#pragma unroll
            for (int a = 0; a < 4; ++a) {
                int jg = j0 + tx + 16 * a;
                float s = (s1[u][a] + s2[u][a] + ck[tx + 16 * a]
                           + crk[rb + 16 * (a - u + 3)]) * scl;
                if (jg > ig + CMEM) s = -1e30f;
                sr[a] = s;
                tmax = fmaxf(tmax, s);
            }
#pragma unroll
            for (int off = 8; off > 0; off >>= 1)
                tmax = fmaxf(tmax, __shfl_xor_sync(0xffffffffu, tmax, off));
            float mnew = fmaxf(mrun[u], tmax);
            float corr = __expf(mrun[u] - mnew);
            float rs = 0.f;
#pragma unroll
            for (int a = 0; a < 4; ++a) {
                float p = __expf(sr[a] - mnew);
                sp[(ty + 16 * u) * 65 + tx + 16 * a] = p;
                rs += p;
            }
#pragma unroll
            for (int off = 8; off > 0; off >>= 1)
                rs += __shfl_xor_sync(0xffffffffu, rs, off);
            mrun[u] = mnew;
            lrun[u] = lrun[u] * corr + rs;
#pragma unroll
            for (int w = 0; w < 4; ++w) o[u][w] *= corr;
        }
        __syncwarp();   // sp rows are produced/consumed within one warp

        // PV: o[u][0..3] over dims tx*4..tx*4+3
#pragma unroll 4
        for (int j = 0; j < 64; ++j) {
            float4 v4 = *(const float4*)&sv[j * 68 + tx * 4];
#pragma unroll
            for (int u = 0; u < 4; ++u) {
                float p = sp[(ty + 16 * u) * 65 + j];
                o[u][0] = fmaf(p, v4.x, o[u][0]);
                o[u][1] = fmaf(p, v4.y, o[u][1]);
                o[u][2] = fmaf(p, v4.z, o[u][2]);
                o[u][3] = fmaf(p, v4.w, o[u][3]);
            }
        }
        __syncthreads();   // before next tile's SMEM overwrite
    }

    // normalize + write attn_vec
#pragma unroll
    for (int u = 0; u < 4; ++u) {
        float inv = 1.f / lrun[u];
        float4 ov = make_float4(o[u][0] * inv, o[u][1] * inv,
                                o[u][2] * inv, o[u][3] * inv);
        *(float4*)&g_av[(long)(b * CQLEN + i0 + ty + 16 * u) * CDM
                        + h * CDH + tx * 4] = ov;
    }
}

// ============================== launch ======================================
extern "C" void kernel_launch(void* const* d_in, const int* in_sizes, int n_in,
                              void* d_out, int out_size) {
    const float* w    = (const float*)d_in[0];
    const float* r    = (const float*)d_in[1];
    const float* rwb  = (const float*)d_in[2];
    const float* rrb  = (const float*)d_in[3];
    const float* Wq   = (const float*)d_in[4];
    const float* Wkv  = (const float*)d_in[5];
    const float* Wr   = (const float*)d_in[6];
    const float* Wo   = (const float*)d_in[7];
    float* out = (float*)d_out;
    (void)in_sizes; (void)n_in; (void)out_size;  // attn_mask/qlen derived analytically

    float *qp, *kvp, *rkp, *avp;
    cudaGetSymbolAddress((void**)&qp,  g_q);
    cudaGetSymbolAddress((void**)&kvp, g_kv);
    cudaGetSymbolAddress((void**)&rkp, g_rk);
    cudaGetSymbolAddress((void**)&avp, g_av);

    // q = w[:, 1024:, :] @ Wq   (per-batch strided)
    sgemm128<<<dim3(8, 8, 4), 256>>>(w + (long)CQLEN * CDM, Wq, qp,
                                     CDM, CDM, (long)CKLEN * CDM, (long)CQLEN * CDM);
    // kv = w @ Wkv   ([8192,1024] @ [1024,2048])
    sgemm128<<<dim3(16, 64, 1), 256>>>(w, Wkv, kvp, 2 * CDM, CDM, 0, 0);
    // rk = r @ Wr    ([2048,1024] @ [1024,1024])
    sgemm128<<<dim3(8, 16, 1), 256>>>(r, Wr, rkp, CDM, CDM, 0, 0);

    // fused relative attention
    size_t shmem = (size_t)(64 * 65 * 3 + 128 * 65 + 64 * 68 + 64 + 128 + 64 + 64)
                   * sizeof(float);   // 101,888 B
    cudaFuncSetAttribute(attn_kernel,
                         cudaFuncAttributeMaxDynamicSharedMemorySize, (int)shmem);
    attn_kernel<<<dim3(16, CNH, CBSZ), 256, shmem>>>(rwb, rrb);

    // out = attn_vec @ Wo   ([4096,1024] @ [1024,1024])
    sgemm128<<<dim3(8, 32, 1), 256>>>(avp, Wo, out, CDM, CDM, 0, 0);
}

// round 10
// speedup vs baseline: 1.0280x; 1.0280x over previous
#include <cuda_runtime.h>

// ---------------- problem constants (hardcoded from reference) -------------
#define CBSZ  4
#define CQLEN 1024
#define CKLEN 2048
#define CNH   16
#define CDH   64
#define CDM   1024
#define CMEM  1024   // MEM_LEN = KLEN - QLEN

// ---------------- scratch (device globals; no allocations allowed) ---------
__device__ float g_q [CBSZ * CQLEN * CDM];            // 16 MB  q[b,i,h*64+d]
__device__ float g_kv[(long)CBSZ * CKLEN * 2 * CDM];  // 64 MB  kv[b,j, (k|v)]
__device__ float g_rk[CKLEN * CDM];                   //  8 MB  rk[m,h*64+d]
__device__ float g_av[CBSZ * CQLEN * CDM];            // 16 MB  attn_vec

// ======================= SGEMM: C = A @ B (row-major) ======================
// 128x128 block tile, BK=16, 256 threads, 8x8 per thread.
// All dims used here are multiples of 128 / 16 -> no bounds checks.
__global__ __launch_bounds__(256, 2)
void sgemm128(const float* __restrict__ A, const float* __restrict__ B,
              float* __restrict__ C, int N, int K, long sA, long sC) {
    __shared__ float As[16][128];
    __shared__ float Bs[16][132];

    const float* Ab = A + (long)blockIdx.z * sA;
    float*       Cb = C + (long)blockIdx.z * sC;
    const int m0 = blockIdx.y * 128;
    const int n0 = blockIdx.x * 128;
    const int tid = threadIdx.x;
    const int tr = tid >> 4;      // 0..15
    const int tc = tid & 15;      // 0..15

    float acc[8][8];
#pragma unroll
    for (int u = 0; u < 8; ++u)
#pragma unroll
        for (int w = 0; w < 8; ++w) acc[u][w] = 0.f;

    for (int k0 = 0; k0 < K; k0 += 16) {
        // A tile: 128 rows x 16 cols, stored transposed As[k][m]
#pragma unroll
        for (int it = 0; it < 2; ++it) {
            int idx = it * 256 + tid;          // float4 index, 512 total
            int r  = idx >> 2;                 // 0..127
            int c4 = (idx & 3) << 2;           // 0,4,8,12
            float4 v = *(const float4*)&Ab[(long)(m0 + r) * K + k0 + c4];
            As[c4 + 0][r] = v.x; As[c4 + 1][r] = v.y;
            As[c4 + 2][r] = v.z; As[c4 + 3][r] = v.w;
        }
        // B tile: 16 rows x 128 cols
#pragma unroll
        for (int it = 0; it < 2; ++it) {
            int idx = it * 256 + tid;
            int r  = idx >> 5;                 // 0..15
            int c4 = (idx & 31) << 2;          // 0..124
            *(float4*)&Bs[r][c4] = *(const float4*)&B[(long)(k0 + r) * N + n0 + c4];
        }
        __syncthreads();
#pragma unroll
        for (int kk = 0; kk < 16; ++kk) {
            float a[8], bb[8];
            *(float4*)&a[0]  = *(const float4*)&As[kk][tr * 8];
            *(float4*)&a[4]  = *(const float4*)&As[kk][tr * 8 + 4];
            *(float4*)&bb[0] = *(const float4*)&Bs[kk][tc * 8];
            *(float4*)&bb[4] = *(const float4*)&Bs[kk][tc * 8 + 4];
#pragma unroll
            for (int u = 0; u < 8; ++u)
#pragma unroll
                for (int w = 0; w < 8; ++w)
                    acc[u][w] = fmaf(a[u], bb[w], acc[u][w]);
        }
        __syncthreads();
    }
#pragma unroll
    for (int u = 0; u < 8; ++u) {
        long row = m0 + tr * 8 + u;
        float4 o0 = make_float4(acc[u][0], acc[u][1], acc[u][2], acc[u][3]);
        float4 o1 = make_float4(acc[u][4], acc[u][5], acc[u][6], acc[u][7]);
        *(float4*)&Cb[row * N + n0 + tc * 8]     = o0;
        *(float4*)&Cb[row * N + n0 + tc * 8 + 4] = o1;
    }
}

// =================== Fused rel-attention (flash-style) =====================
// score[i,j] = ( q_i·k_j + q_i·rk_m + rwb·k_j + rrb·rk_m ) * 1/8,
//   m = j - i + 1023, valid iff j <= i + 1024 (== rel-shift in-range region).
// Block: one (b, h, 64-query i-tile). j-tiles of 64. rk band of 128 rows.
// Thread map: ty=tid/16 tx=tid%16; thread covers rows {ty+16u}, cols {tx+16a}.
// -> rk band row index = (tx - ty + 15) + 16*(a-u+3), steps by 1 across tx
//    (bank-friendly with stride-65 SMEM rows).
__global__ __launch_bounds__(256, 2)
void attn_kernel(const float* __restrict__ rwbias, const float* __restrict__ rrbias) {
    extern __shared__ float smf[];
    float* sq  = smf;               // 64 x 65
    float* sk  = sq  + 64 * 65;     // 64 x 65
    float* sp  = sk  + 64 * 65;     // 64 x 65 (probabilities)
    float* srk = sp  + 64 * 65;     // 128 x 65 (rk band)
    float* sv  = srk + 128 * 65;    // 64 x 68 (16B-aligned rows for float4)
    float* ck  = sv  + 64 * 68;     // 64   rwb·k_j
    float* crk = ck  + 64;          // 128  rrb·rk_m
    float* rwb = crk + 128;         // 64
    float* rrb = rwb + 64;          // 64

    const int it0 = blockIdx.x;     // i-tile (0..15)
    const int h   = blockIdx.y;
    const int b   = blockIdx.z;
    const int i0  = it0 * 64;
    const int tid = threadIdx.x;
    const int ty  = tid >> 4;       // 0..15
    const int tx  = tid & 15;       // 0..15

    if (tid < 64)        rwb[tid]      = rwbias[h * 64 + tid];
    else if (tid < 128)  rrb[tid - 64] = rrbias[h * 64 + (tid - 64)];

    // q tile (raw q; biases folded via ck/crk scalars)
#pragma unroll
    for (int e = 0; e < 16; ++e) {
        int idx = e * 256 + tid;
        int rr = idx >> 6, d = idx & 63;
        sq[rr * 65 + d] = g_q[(long)(b * CQLEN + i0 + rr) * CDM + h * CDH + d];
    }
    __syncthreads();

    float o[4][4];
    float mrun[4], lrun[4];
#pragma unroll
    for (int u = 0; u < 4; ++u) {
        mrun[u] = -1e30f; lrun[u] = 0.f;
#pragma unroll
        for (int w = 0; w < 4; ++w) o[u][w] = 0.f;
    }

    const int rb  = tx - ty + 15;        // band base row (0..30)
    const int njt = it0 + 17;            // last tile with any valid j

    for (int jt = 0; jt < njt; ++jt) {
        const int j0 = jt * 64;
        const int m0 = j0 - i0 + 960;    // band start (>= 0 always)

        // load k, v tiles
#pragma unroll
        for (int e = 0; e < 16; ++e) {
            int idx = e * 256 + tid;
            int rr = idx >> 6, d = idx & 63;
            long base = (long)(b * CKLEN + j0 + rr) * (2 * CDM) + h * CDH + d;
            sk[rr * 65 + d] = g_kv[base];
            sv[rr * 68 + d] = g_kv[base + CDM];
        }
        // load rk band (128 rows; clamp — overflow rows only feed masked entries)
#pragma unroll
        for (int e = 0; e < 32; ++e) {
            int idx = e * 256 + tid;
            int rr = idx >> 6, d = idx & 63;
            int m = m0 + rr; if (m > CKLEN - 1) m = CKLEN - 1;
            srk[rr * 65 + d] = g_rk[(long)m * CDM + h * CDH + d];
        }
        __syncthreads();

        // per-column bias scalars
        if (tid < 64) {
            float s = 0.f;
            for (int d = 0; d < 64; ++d) s = fmaf(rwb[d], sk[tid * 65 + d], s);
            ck[tid] = s;
        } else if (tid < 192) {
            int t = tid - 64;
            float s = 0.f;
            for (int d = 0; d < 64; ++d) s = fmaf(rrb[d], srk[t * 65 + d], s);
            crk[t] = s;
        }
        __syncthreads();

        // scores: two length-64 dots per (i,j)
        float s1[4][4], s2[4][4];
#pragma unroll
        for (int u = 0; u < 4; ++u)
#pragma unroll
            for (int a = 0; a < 4; ++a) { s1[u][a] = 0.f; s2[u][a] = 0.f; }

#pragma unroll 4
        for (int d = 0; d < 64; ++d) {
            float qv[4], kvv[4], rv[7];
#pragma unroll
            for (int u = 0; u < 4; ++u) qv[u]  = sq[(ty + 16 * u) * 65 + d];
#pragma unroll
            for (int a = 0; a < 4; ++a) kvv[a] = sk[(tx + 16 * a) * 65 + d];
#pragma unroll
            for (int t = 0; t < 7; ++t) rv[t]  = srk[(rb + 16 * t) * 65 + d];
#pragma unroll
            for (int u = 0; u < 4; ++u)
#pragma unroll
                for (int a = 0; a < 4; ++a) {
                    s1[u][a] = fmaf(qv[u], kvv[a],        s1[u][a]);
                    s2[u][a] = fmaf(qv[u], rv[a - u + 3], s2[u][a]);
                }
        }

        // online softmax (row reduce across the 16 tx lanes of each half-warp)
        const float scl = 0.125f;
#pragma unroll
        for (int u = 0; u < 4; ++u) {
            const int ig = i0 + ty + 16 * u;
            float sr[4], tmax = -1e30f;
#pragma unroll
            for (int a = 0; a < 4; ++a) {
                int jg = j0 + tx + 16 * a;
                float s = (s1[u][a] + s2[u][a] + ck[tx + 16 * a]
                           + crk[rb + 16 * (a - u + 3)]) * scl;
                if (jg > ig + CMEM) s = -1e30f;
                sr[a] = s;
                tmax = fmaxf(tmax, s);
            }
#pragma unroll
            for (int off = 8; off > 0; off >>= 1)
                tmax = fmaxf(tmax, __shfl_xor_sync(0xffffffffu, tmax, off));
            float mnew = fmaxf(mrun[u], tmax);
            float corr = __expf(mrun[u] - mnew);
            float rs = 0.f;
#pragma unroll
            for (int a = 0; a < 4; ++a) {
                float p = __expf(sr[a] - mnew);
                sp[(ty + 16 * u) * 65 + tx + 16 * a] = p;
                rs += p;
            }
#pragma unroll
            for (int off = 8; off > 0; off >>= 1)
                rs += __shfl_xor_sync(0xffffffffu, rs, off);
            mrun[u] = mnew;
            lrun[u] = lrun[u] * corr + rs;
#pragma unroll
            for (int w = 0; w < 4; ++w) o[u][w] *= corr;
        }
        __syncwarp();   // sp rows are produced/consumed within one warp

        // PV: o[u][0..3] over dims tx*4..tx*4+3
#pragma unroll 4
        for (int j = 0; j < 64; ++j) {
            float4 v4 = *(const float4*)&sv[j * 68 + tx * 4];
#pragma unroll
            for (int u = 0; u < 4; ++u) {
                float p = sp[(ty + 16 * u) * 65 + j];
                o[u][0] = fmaf(p, v4.x, o[u][0]);
                o[u][1] = fmaf(p, v4.y, o[u][1]);
                o[u][2] = fmaf(p, v4.z, o[u][2]);
                o[u][3] = fmaf(p, v4.w, o[u][3]);
            }
        }
        __syncthreads();   // before next tile's SMEM overwrite
    }

    // normalize + write attn_vec
#pragma unroll
    for (int u = 0; u < 4; ++u) {
        float inv = 1.f / lrun[u];
        float4 ov = make_float4(o[u][0] * inv, o[u][1] * inv,
                                o[u][2] * inv, o[u][3] * inv);
        *(float4*)&g_av[(long)(b * CQLEN + i0 + ty + 16 * u) * CDM
                        + h * CDH + tx * 4] = ov;
    }
}

// ============================== launch ======================================
extern "C" void kernel_launch(void* const* d_in, const int* in_sizes, int n_in,
                              void* d_out, int out_size) {
    const float* w    = (const float*)d_in[0];
    const float* r    = (const float*)d_in[1];
    const float* rwb  = (const float*)d_in[2];
    const float* rrb  = (const float*)d_in[3];
    const float* Wq   = (const float*)d_in[4];
    const float* Wkv  = (const float*)d_in[5];
    const float* Wr   = (const float*)d_in[6];
    const float* Wo   = (const float*)d_in[7];
    float* out = (float*)d_out;
    (void)in_sizes; (void)n_in; (void)out_size;  // attn_mask/qlen derived analytically

    float *qp, *kvp, *rkp, *avp;
    cudaGetSymbolAddress((void**)&qp,  g_q);
    cudaGetSymbolAddress((void**)&kvp, g_kv);
    cudaGetSymbolAddress((void**)&rkp, g_rk);
    cudaGetSymbolAddress((void**)&avp, g_av);

    // q = w[:, 1024:, :] @ Wq   (per-batch strided)
    sgemm128<<<dim3(8, 8, 4), 256>>>(w + (long)CQLEN * CDM, Wq, qp,
                                     CDM, CDM, (long)CKLEN * CDM, (long)CQLEN * CDM);
    // kv = w @ Wkv   ([8192,1024] @ [1024,2048])
    sgemm128<<<dim3(16, 64, 1), 256>>>(w, Wkv, kvp, 2 * CDM, CDM, 0, 0);
    // rk = r @ Wr    ([2048,1024] @ [1024,1024])
    sgemm128<<<dim3(8, 16, 1), 256>>>(r, Wr, rkp, CDM, CDM, 0, 0);

    // fused relative attention
    size_t shmem = (size_t)(64 * 65 * 3 + 128 * 65 + 64 * 68 + 64 + 128 + 64 + 64)
                   * sizeof(float);   // 101,888 B
    cudaFuncSetAttribute(attn_kernel,
                         cudaFuncAttributeMaxDynamicSharedMemorySize, (int)shmem);
    attn_kernel<<<dim3(16, CNH, CBSZ), 256, shmem>>>(rwb, rrb);

    // out = attn_vec @ Wo   ([4096,1024] @ [1024,1024])
    sgemm128<<<dim3(8, 32, 1), 256>>>(avp, Wo, out, CDM, CDM, 0, 0);
}